// round 13
// baseline (speedup 1.0000x reference)
#include <cuda_runtime.h>
#include <cuda_bf16.h>
#include <cstdint>

constexpr int B = 2, C = 2, D = 160, H = 192, W = 224;
constexpr int HW  = H * W;          // 43008
constexpr int DHW = D * H * W;      // 6,881,280
constexpr int VPT = 4;              // voxels (z-chain length) per thread

__device__ __forceinline__ float lerpf(float a, float b, float t) {
    return fmaf(t, b - a, a);
}

__global__ __launch_bounds__(224, 7)
void affine_grid_sample_kernel(const float* __restrict__ src,
                               const float* __restrict__ mat,
                               float* __restrict__ out)
{
    const int w  = threadIdx.x;      // 0..W-1
    const int h  = blockIdx.y;       // 0..H-1
    const int zz = blockIdx.z;       // 0..B*(D/VPT)-1
    const int b  = (zz >= D / VPT) ? 1 : 0;
    const int d0 = VPT * (zz - (b ? D / VPT : 0));

    const float4* m4 = (const float4*)(mat + b * 12);
    const float4 r0 = __ldg(m4 + 0);
    const float4 r1 = __ldg(m4 + 1);
    const float4 r2 = __ldg(m4 + 2);

    // voxel 0 (d0) coordinates
    const float x = fmaf((float)w,  2.0f / (W - 1), -1.0f);
    const float y = fmaf((float)h,  2.0f / (H - 1), -1.0f);
    const float z = fmaf((float)d0, 2.0f / (D - 1), -1.0f);

    const float gx = fmaf(r0.x, x, fmaf(r0.y, y, fmaf(r0.z, z, r0.w * (1.0f / D))));
    const float gy = fmaf(r1.x, x, fmaf(r1.y, y, fmaf(r1.z, z, r1.w * (1.0f / H))));
    const float gz = fmaf(r2.x, x, fmaf(r2.y, y, fmaf(r2.z, z, r2.w * (1.0f / W))));

    const float ix0 = (gx + 1.0f) * (0.5f * (W - 1));
    const float iy0 = (gy + 1.0f) * (0.5f * (H - 1));
    const float iz0 = (gz + 1.0f) * (0.5f * (D - 1));

    // per-d-step deltas (constant per batch)
    const float ddz = 2.0f / (D - 1);
    const float dix = r0.z * (ddz * 0.5f * (W - 1));
    const float diy = r1.z * (ddz * 0.5f * (H - 1));
    const float diz = r2.z * (ddz * 0.5f * (D - 1));

    const float* sb = src + (size_t)b * (size_t)(C * DHW);
    const size_t ob = (size_t)b * (size_t)(C * DHW) + (size_t)((d0 * H + h) * W + w);

    // ---- interior test for the whole chain ----
    bool interior = true;
#pragma unroll
    for (int v = 0; v < VPT; ++v) {
        const float ix = fmaf((float)v, dix, ix0);
        const float iy = fmaf((float)v, diy, iy0);
        const float iz = fmaf((float)v, diz, iz0);
        const int x0 = (int)floorf(ix);
        const int y0 = (int)floorf(iy);
        const int z0 = (int)floorf(iz);
        interior &= ((unsigned)x0 < (unsigned)(W - 1)) &
                    ((unsigned)y0 < (unsigned)(H - 1)) &
                    ((unsigned)z0 < (unsigned)(D - 1));
    }

    if (interior) {
        // ======== fast path: chain-shared planes, unpredicated loads ========
#pragma unroll
        for (int ch = 0; ch < 2; ++ch) {
            const float* base = sb + (size_t)ch * DHW;

            float pu00, pu01, pu10, pu11;   // previous voxel's upper plane
            int   px0 = 0, py0 = 0, pz0 = 0;

#pragma unroll
            for (int v = 0; v < VPT; ++v) {
                const float ix = fmaf((float)v, dix, ix0);
                const float iy = fmaf((float)v, diy, iy0);
                const float iz = fmaf((float)v, diz, iz0);
                const float fx0 = floorf(ix), fy0 = floorf(iy), fz0 = floorf(iz);
                const float fx = ix - fx0, fy = iy - fy0, fz = iz - fz0;
                const int x0 = (int)fx0, y0 = (int)fy0, z0 = (int)fz0;

                const float* p = base + ((size_t)((z0 * H + y0) * W + x0));

                // upper plane: always loaded
                const float u00 = __ldg(p + HW);
                const float u01 = __ldg(p + HW + 1);
                const float u10 = __ldg(p + HW + W);
                const float u11 = __ldg(p + HW + W + 1);

                float l00, l01, l10, l11;
                if (v == 0) {
                    l00 = __ldg(p);
                    l01 = __ldg(p + 1);
                    l10 = __ldg(p + W);
                    l11 = __ldg(p + W + 1);
                } else {
                    const bool sh = (z0 == pz0 + 1) & (y0 == py0) & (x0 == px0);
                    l00 = sh ? pu00 : __ldg(p);
                    l01 = sh ? pu01 : __ldg(p + 1);
                    l10 = sh ? pu10 : __ldg(p + W);
                    l11 = sh ? pu11 : __ldg(p + W + 1);
                }

                const float m0 = lerpf(lerpf(l00, l01, fx), lerpf(l10, l11, fx), fy);
                const float m1 = lerpf(lerpf(u00, u01, fx), lerpf(u10, u11, fx), fy);
                out[ob + (size_t)v * HW + (size_t)ch * DHW] = lerpf(m0, m1, fz);

                pu00 = u00; pu01 = u01; pu10 = u10; pu11 = u11;
                px0 = x0; py0 = y0; pz0 = z0;
            }

            // keep channel 1's loads out of channel 0's register window
            asm volatile("" ::: "memory");
        }
        return;
    }

    // ======== border path: per-voxel fully predicated, zero padding ========
#pragma unroll
    for (int v = 0; v < VPT; ++v) {
        const float ix = fmaf((float)v, dix, ix0);
        const float iy = fmaf((float)v, diy, iy0);
        const float iz = fmaf((float)v, diz, iz0);
        const float fx0 = floorf(ix), fy0 = floorf(iy), fz0 = floorf(iz);
        const float fx = ix - fx0, fy = iy - fy0, fz = iz - fz0;
        const int x0 = (int)fx0, y0 = (int)fy0, z0 = (int)fz0;

        const bool vx0 = (unsigned)x0       < (unsigned)W;
        const bool vx1 = (unsigned)(x0 + 1) < (unsigned)W;
        const bool vy0 = (unsigned)y0       < (unsigned)H;
        const bool vy1 = (unsigned)(y0 + 1) < (unsigned)H;
        const bool vz0 = (unsigned)z0       < (unsigned)D;
        const bool vz1 = (unsigned)(z0 + 1) < (unsigned)D;

        const bool p000 = vz0 & vy0 & vx0, p001 = vz0 & vy0 & vx1;
        const bool p010 = vz0 & vy1 & vx0, p011 = vz0 & vy1 & vx1;
        const bool p100 = vz1 & vy0 & vx0, p101 = vz1 & vy0 & vx1;
        const bool p110 = vz1 & vy1 & vx0, p111 = vz1 & vy1 & vx1;

        const float* pbase = sb + ((size_t)((z0 * H + y0) * W + x0));

#pragma unroll
        for (int ch = 0; ch < 2; ++ch) {
            const float* p = pbase + (size_t)ch * DHW;

            float l00 = p000 ? __ldg(p)              : 0.0f;
            float l01 = p001 ? __ldg(p + 1)          : 0.0f;
            float l10 = p010 ? __ldg(p + W)          : 0.0f;
            float l11 = p011 ? __ldg(p + W + 1)      : 0.0f;
            float u00 = p100 ? __ldg(p + HW)         : 0.0f;
            float u01 = p101 ? __ldg(p + HW + 1)     : 0.0f;
            float u10 = p110 ? __ldg(p + HW + W)     : 0.0f;
            float u11 = p111 ? __ldg(p + HW + W + 1) : 0.0f;

            const float m0 = lerpf(lerpf(l00, l01, fx), lerpf(l10, l11, fx), fy);
            const float m1 = lerpf(lerpf(u00, u01, fx), lerpf(u10, u11, fx), fy);
            out[ob + (size_t)v * HW + (size_t)ch * DHW] = lerpf(m0, m1, fz);
        }
    }
}

extern "C" void kernel_launch(void* const* d_in, const int* in_sizes, int n_in,
                              void* d_out, int out_size)
{
    const float* src = (const float*)d_in[0];
    const float* mat = (const float*)d_in[1];
    float* out = (float*)d_out;

    dim3 block(W, 1, 1);                 // 224 threads = 7 warps
    dim3 grid(1, H, B * (D / VPT));      // (1, 192, 80)
    affine_grid_sample_kernel<<<grid, block>>>(src, mat, out);
}

// round 14
// speedup vs baseline: 1.4460x; 1.4460x over previous
#include <cuda_runtime.h>
#include <cuda_bf16.h>
#include <cstdint>

constexpr int B = 2, C = 2, D = 160, H = 192, W = 224;
constexpr int HW  = H * W;          // 43008
constexpr int DHW = D * H * W;      // 6,881,280

__device__ __forceinline__ float lerpf(float a, float b, float t) {
    return fmaf(t, b - a, a);
}

// Guaranteed-predicated global load: returns *p when cond, else fallback,
// emitting @p LDG (dest preserved when predicated off) — never LDG+SEL.
__device__ __forceinline__ float ldg_if(const float* p, unsigned cond, float fallback) {
    float v = fallback;
    asm volatile("{\n\t"
                 ".reg .pred p0;\n\t"
                 "setp.ne.u32 p0, %1, 0;\n\t"
                 "@p0 ld.global.nc.f32 %0, [%2];\n\t"
                 "}"
                 : "+f"(v) : "r"(cond), "l"(p));
    return v;
}

__global__ __launch_bounds__(224, 7)
void affine_grid_sample_kernel(const float* __restrict__ src,
                               const float* __restrict__ mat,
                               float* __restrict__ out)
{
    const int w  = threadIdx.x;      // 0..W-1
    const int h  = blockIdx.y;       // 0..H-1
    const int zz = blockIdx.z;       // 0..B*(D/2)-1
    const int b  = (zz >= D / 2) ? 1 : 0;
    const int d0 = 2 * (zz - (b ? D / 2 : 0));   // this thread does d0 and d0+1

    const float4* m4 = (const float4*)(mat + b * 12);
    const float4 r0 = __ldg(m4 + 0);
    const float4 r1 = __ldg(m4 + 1);
    const float4 r2 = __ldg(m4 + 2);

    // voxel A (d0) coordinates
    const float x = fmaf((float)w,  2.0f / (W - 1), -1.0f);
    const float y = fmaf((float)h,  2.0f / (H - 1), -1.0f);
    const float z = fmaf((float)d0, 2.0f / (D - 1), -1.0f);

    const float gxA = fmaf(r0.x, x, fmaf(r0.y, y, fmaf(r0.z, z, r0.w * (1.0f / D))));
    const float gyA = fmaf(r1.x, x, fmaf(r1.y, y, fmaf(r1.z, z, r1.w * (1.0f / H))));
    const float gzA = fmaf(r2.x, x, fmaf(r2.y, y, fmaf(r2.z, z, r2.w * (1.0f / W))));

    const float ixA = (gxA + 1.0f) * (0.5f * (W - 1));
    const float iyA = (gyA + 1.0f) * (0.5f * (H - 1));
    const float izA = (gzA + 1.0f) * (0.5f * (D - 1));

    // voxel B (d0+1) = A + constant z-step delta
    const float ddz = 2.0f / (D - 1);
    const float ixB = fmaf(r0.z, ddz * (0.5f * (W - 1)), ixA);
    const float iyB = fmaf(r1.z, ddz * (0.5f * (H - 1)), iyA);
    const float izB = fmaf(r2.z, ddz * (0.5f * (D - 1)), izA);

    const float fxA0 = floorf(ixA), fyA0 = floorf(iyA), fzA0 = floorf(izA);
    const float fxB0 = floorf(ixB), fyB0 = floorf(iyB), fzB0 = floorf(izB);
    const float fxA = ixA - fxA0, fyA = iyA - fyA0, fzA = izA - fzA0;
    const float fxB = ixB - fxB0, fyB = iyB - fyB0, fzB = izB - fzB0;
    const int xA0 = (int)fxA0, yA0 = (int)fyA0, zA0 = (int)fzA0;
    const int xB0 = (int)fxB0, yB0 = (int)fyB0, zB0 = (int)fzB0;

    // B's lower plane coincides with A's upper plane when:
    const bool sh = (zB0 == zA0 + 1) & (yB0 == yA0) & (xB0 == xA0);
    const unsigned needB = sh ? 0u : 1u;   // fixup load predicate

    const float* sb = src + (size_t)b * (size_t)(C * DHW);
    const float* pA = sb + ((size_t)((zA0 * H + yA0) * W + xA0));
    const float* pB = sb + ((size_t)((zB0 * H + yB0) * W + xB0));

    const size_t obA = (size_t)b * (size_t)(C * DHW) + (size_t)((d0 * H + h) * W + w);

    const bool interior =
        ((unsigned)xA0 < (unsigned)(W - 1)) & ((unsigned)yA0 < (unsigned)(H - 1)) &
        ((unsigned)zA0 < (unsigned)(D - 1)) &
        ((unsigned)xB0 < (unsigned)(W - 1)) & ((unsigned)yB0 < (unsigned)(H - 1)) &
        ((unsigned)zB0 < (unsigned)(D - 1));

    if (interior) {
        // =========== fast path: unpredicated loads (~96% of threads) ===========
        // ---- channel 0 ----
        {
            float a000 = __ldg(pA);
            float a001 = __ldg(pA + 1);
            float a010 = __ldg(pA + W);
            float a011 = __ldg(pA + W + 1);
            float a100 = __ldg(pA + HW);
            float a101 = __ldg(pA + HW + 1);
            float a110 = __ldg(pA + HW + W);
            float a111 = __ldg(pA + HW + W + 1);

            float bu00 = __ldg(pB + HW);
            float bu01 = __ldg(pB + HW + 1);
            float bu10 = __ldg(pB + HW + W);
            float bu11 = __ldg(pB + HW + W + 1);

            // B lower plane: A's upper plane for ~88% of lanes; guaranteed-
            // predicated fixup LDG otherwise (no LDG+SEL fallback possible)
            float bl00 = ldg_if(pB,         needB, a100);
            float bl01 = ldg_if(pB + 1,     needB, a101);
            float bl10 = ldg_if(pB + W,     needB, a110);
            float bl11 = ldg_if(pB + W + 1, needB, a111);

            float l0 = lerpf(lerpf(a000, a001, fxA), lerpf(a010, a011, fxA), fyA);
            float l1 = lerpf(lerpf(a100, a101, fxA), lerpf(a110, a111, fxA), fyA);
            out[obA] = lerpf(l0, l1, fzA);

            float m0 = lerpf(lerpf(bl00, bl01, fxB), lerpf(bl10, bl11, fxB), fyB);
            float m1 = lerpf(lerpf(bu00, bu01, fxB), lerpf(bu10, bu11, fxB), fyB);
            out[obA + HW] = lerpf(m0, m1, fzB);
        }

        asm volatile("" ::: "memory");

        // ---- channel 1 ----
        {
            const float* qA = pA + DHW;
            const float* qB = pB + DHW;

            float a000 = __ldg(qA);
            float a001 = __ldg(qA + 1);
            float a010 = __ldg(qA + W);
            float a011 = __ldg(qA + W + 1);
            float a100 = __ldg(qA + HW);
            float a101 = __ldg(qA + HW + 1);
            float a110 = __ldg(qA + HW + W);
            float a111 = __ldg(qA + HW + W + 1);

            float bu00 = __ldg(qB + HW);
            float bu01 = __ldg(qB + HW + 1);
            float bu10 = __ldg(qB + HW + W);
            float bu11 = __ldg(qB + HW + W + 1);

            float bl00 = ldg_if(qB,         needB, a100);
            float bl01 = ldg_if(qB + 1,     needB, a101);
            float bl10 = ldg_if(qB + W,     needB, a110);
            float bl11 = ldg_if(qB + W + 1, needB, a111);

            float l0 = lerpf(lerpf(a000, a001, fxA), lerpf(a010, a011, fxA), fyA);
            float l1 = lerpf(lerpf(a100, a101, fxA), lerpf(a110, a111, fxA), fyA);
            out[obA + DHW] = lerpf(l0, l1, fzA);

            float m0 = lerpf(lerpf(bl00, bl01, fxB), lerpf(bl10, bl11, fxB), fyB);
            float m1 = lerpf(lerpf(bu00, bu01, fxB), lerpf(bu10, bu11, fxB), fyB);
            out[obA + HW + DHW] = lerpf(m0, m1, fzB);
        }
        return;
    }

    // =========== border path: fully predicated, zero padding ===========
    const bool vAx0 = (unsigned)xA0       < (unsigned)W;
    const bool vAx1 = (unsigned)(xA0 + 1) < (unsigned)W;
    const bool vAy0 = (unsigned)yA0       < (unsigned)H;
    const bool vAy1 = (unsigned)(yA0 + 1) < (unsigned)H;
    const bool vAz0 = (unsigned)zA0       < (unsigned)D;
    const bool vAz1 = (unsigned)(zA0 + 1) < (unsigned)D;
    const bool vBx0 = (unsigned)xB0       < (unsigned)W;
    const bool vBx1 = (unsigned)(xB0 + 1) < (unsigned)W;
    const bool vBy0 = (unsigned)yB0       < (unsigned)H;
    const bool vBy1 = (unsigned)(yB0 + 1) < (unsigned)H;
    const bool vBz0 = (unsigned)zB0       < (unsigned)D;
    const bool vBz1 = (unsigned)(zB0 + 1) < (unsigned)D;

    const bool pA000 = vAz0 & vAy0 & vAx0, pA001 = vAz0 & vAy0 & vAx1;
    const bool pA010 = vAz0 & vAy1 & vAx0, pA011 = vAz0 & vAy1 & vAx1;
    const bool pA100 = vAz1 & vAy0 & vAx0, pA101 = vAz1 & vAy0 & vAx1;
    const bool pA110 = vAz1 & vAy1 & vAx0, pA111 = vAz1 & vAy1 & vAx1;
    const bool pB000 = vBz0 & vBy0 & vBx0, pB001 = vBz0 & vBy0 & vBx1;
    const bool pB010 = vBz0 & vBy1 & vBx0, pB011 = vBz0 & vBy1 & vBx1;
    const bool pB100 = vBz1 & vBy0 & vBx0, pB101 = vBz1 & vBy0 & vBx1;
    const bool pB110 = vBz1 & vBy1 & vBx0, pB111 = vBz1 & vBy1 & vBx1;

#pragma unroll
    for (int ch = 0; ch < 2; ++ch) {
        const float* fA = pA + ch * DHW;
        const float* fB = pB + ch * DHW;

        float a000 = pA000 ? __ldg(fA)              : 0.0f;
        float a001 = pA001 ? __ldg(fA + 1)          : 0.0f;
        float a010 = pA010 ? __ldg(fA + W)          : 0.0f;
        float a011 = pA011 ? __ldg(fA + W + 1)      : 0.0f;
        float a100 = pA100 ? __ldg(fA + HW)         : 0.0f;
        float a101 = pA101 ? __ldg(fA + HW + 1)     : 0.0f;
        float a110 = pA110 ? __ldg(fA + HW + W)     : 0.0f;
        float a111 = pA111 ? __ldg(fA + HW + W + 1) : 0.0f;

        float bu00 = pB100 ? __ldg(fB + HW)         : 0.0f;
        float bu01 = pB101 ? __ldg(fB + HW + 1)     : 0.0f;
        float bu10 = pB110 ? __ldg(fB + HW + W)     : 0.0f;
        float bu11 = pB111 ? __ldg(fB + HW + W + 1) : 0.0f;

        float bl00 = pB000 ? __ldg(fB)              : 0.0f;
        float bl01 = pB001 ? __ldg(fB + 1)          : 0.0f;
        float bl10 = pB010 ? __ldg(fB + W)          : 0.0f;
        float bl11 = pB011 ? __ldg(fB + W + 1)      : 0.0f;

        float l0 = lerpf(lerpf(a000, a001, fxA), lerpf(a010, a011, fxA), fyA);
        float l1 = lerpf(lerpf(a100, a101, fxA), lerpf(a110, a111, fxA), fyA);
        out[obA + ch * DHW] = lerpf(l0, l1, fzA);

        float m0 = lerpf(lerpf(bl00, bl01, fxB), lerpf(bl10, bl11, fxB), fyB);
        float m1 = lerpf(lerpf(bu00, bu01, fxB), lerpf(bu10, bu11, fxB), fyB);
        out[obA + HW + ch * DHW] = lerpf(m0, m1, fzB);
    }
}

extern "C" void kernel_launch(void* const* d_in, const int* in_sizes, int n_in,
                              void* d_out, int out_size)
{
    const float* src = (const float*)d_in[0];
    const float* mat = (const float*)d_in[1];
    float* out = (float*)d_out;

    dim3 block(W, 1, 1);              // 224 threads = 7 warps
    dim3 grid(1, H, B * (D / 2));     // (1, 192, 160)
    affine_grid_sample_kernel<<<grid, block>>>(src, mat, out);
}